// round 15
// baseline (speedup 1.0000x reference)
#include <cuda_runtime.h>
#include <cuda_bf16.h>
#include <math.h>
#include <stdint.h>

#define F 64
#define MAXN 100000
#define MAXE 1600000
#define SLOPE 0.2f
#define KT 32            // GEMM k-chunk staged in smem
#define APAD 72          // bf16 row stride for A/B tiles (conflict-free LDS)

// ---------------- device scratch (static, no runtime alloc) ----------------
__device__ float g_z[(size_t)MAXN * F];     // projected features [N,64]
__device__ int   g_cnt[MAXN];               // in-degree histogram
__device__ int   g_cnt2[MAXN];              // fill cursors
__device__ int   g_tmp[MAXN];               // inclusive scan temp
__device__ int   g_rowptr[MAXN + 1];        // CSR offsets
__device__ int   g_src_sorted[MAXE];        // src ids grouped by dst
__device__ int   g_blocksum[128];
__device__ int   g_blockoff[128];

// ---------------- bf16 HMMA helper (sm_80+; works on plain sm_103) ----------
__device__ __forceinline__ void mma_bf16(float* d,
        uint32_t a0, uint32_t a1, uint32_t a2, uint32_t a3,
        uint32_t b0, uint32_t b1) {
    asm volatile(
        "mma.sync.aligned.m16n8k16.row.col.f32.bf16.bf16.f32 "
        "{%0,%1,%2,%3}, {%4,%5,%6,%7}, {%8,%9}, {%0,%1,%2,%3};"
        : "+f"(d[0]), "+f"(d[1]), "+f"(d[2]), "+f"(d[3])
        : "r"(a0), "r"(a1), "r"(a2), "r"(a3), "r"(b0), "r"(b1));
}

// ---------------- tensor-core projection GEMM (mma.sync bf16 3-term) --------
// blocks [0,nbd): d_sim @ W_d ; blocks [nbd,nbd+nbm): mi_sim @ W_mi.
// Block tile M=128 x N=64; 8 warps, warp w owns rows [16w,16w+16) x all 64 cols.
// Z = A @ W via D[m][n] = sum_k A[m][k] * B[n][k] with B[n][k] = W[k][n].
__global__ void __launch_bounds__(256) gemm_mma(
        const float* __restrict__ d_sim,  const float* __restrict__ W_d,
        const float* __restrict__ mi_sim, const float* __restrict__ W_mi,
        int ND, int NM, int KD, int KM) {
    __shared__ __align__(16) __nv_bfloat16 Ah[128][APAD];
    __shared__ __align__(16) __nv_bfloat16 Al[128][APAD];
    __shared__ __align__(16) __nv_bfloat16 Bh[64][APAD];
    __shared__ __align__(16) __nv_bfloat16 Bl[64][APAD];

    const int nbd = (ND + 127) >> 7;
    const float* A; const float* W; int M, K, zoff, m0;
    if ((int)blockIdx.x < nbd) {
        A = d_sim;  W = W_d;  M = ND; K = KD; zoff = 0;
        m0 = blockIdx.x * 128;
    } else {
        A = mi_sim; W = W_mi; M = NM; K = KM; zoff = ND;
        m0 = (blockIdx.x - nbd) * 128;
    }

    const int tid = threadIdx.x;
    const int w = tid >> 5, lane = tid & 31;
    const int g = lane >> 2, tg = lane & 3;

    float acc[8][4];
#pragma unroll
    for (int t = 0; t < 8; t++)
#pragma unroll
        for (int q = 0; q < 4; q++) acc[t][q] = 0.f;

    const int nchunks = (K + KT - 1) / KT;
    for (int ch = 0; ch < nchunks; ch++) {
        const int kk = ch * KT;

        // ---- stage A chunk [128 x 32] as bf16 hi/lo: thread -> row tid>>1,
        //      cols (tid&1)*16 .. +15 (pairs)
        {
            int r = tid >> 1, c0 = (tid & 1) << 4;
            int row = m0 + r;
            bool rok = (row < M);
            const float* ap = A + (size_t)row * K + kk;
#pragma unroll
            for (int j = 0; j < 16; j += 2) {
                int c = c0 + j;
                float x0 = (rok && kk + c     < K) ? ap[c]     : 0.f;
                float x1 = (rok && kk + c + 1 < K) ? ap[c + 1] : 0.f;
                __nv_bfloat16 h0 = __float2bfloat16(x0);
                __nv_bfloat16 h1 = __float2bfloat16(x1);
                __nv_bfloat16 l0 = __float2bfloat16(x0 - __bfloat162float(h0));
                __nv_bfloat16 l1 = __float2bfloat16(x1 - __bfloat162float(h1));
                *(__nv_bfloat162*)&Ah[r][c] = __nv_bfloat162(h0, h1);
                *(__nv_bfloat162*)&Al[r][c] = __nv_bfloat162(l0, l1);
            }
        }
        // ---- stage B chunk as [n][k] = W[k][n]: thread -> k = tid>>3,
        //      n = (tid&7)*8 .. +7 (coalesced global reads along n)
        {
            int k = tid >> 3, n0 = (tid & 7) << 3;
            bool kok = (kk + k < K);
            const float* wp = W + (size_t)(kk + k) * F;
#pragma unroll
            for (int i = 0; i < 8; i++) {
                int n = n0 + i;
                float x = kok ? wp[n] : 0.f;
                __nv_bfloat16 h = __float2bfloat16(x);
                __nv_bfloat16 l = __float2bfloat16(x - __bfloat162float(h));
                Bh[n][k] = h;
                Bl[n][k] = l;
            }
        }
        __syncthreads();

        // ---- 2 k-steps of m16n8k16 over this chunk
#pragma unroll
        for (int ks = 0; ks < 2; ks++) {
            const int kb = ks * 16;
            const int r0 = w * 16 + g;
            uint32_t ah0 = *(const uint32_t*)&Ah[r0    ][kb + 2 * tg];
            uint32_t ah1 = *(const uint32_t*)&Ah[r0 + 8][kb + 2 * tg];
            uint32_t ah2 = *(const uint32_t*)&Ah[r0    ][kb + 2 * tg + 8];
            uint32_t ah3 = *(const uint32_t*)&Ah[r0 + 8][kb + 2 * tg + 8];
            uint32_t al0 = *(const uint32_t*)&Al[r0    ][kb + 2 * tg];
            uint32_t al1 = *(const uint32_t*)&Al[r0 + 8][kb + 2 * tg];
            uint32_t al2 = *(const uint32_t*)&Al[r0    ][kb + 2 * tg + 8];
            uint32_t al3 = *(const uint32_t*)&Al[r0 + 8][kb + 2 * tg + 8];
#pragma unroll
            for (int t = 0; t < 8; t++) {
                int n = t * 8 + g;
                uint32_t bh0 = *(const uint32_t*)&Bh[n][kb + 2 * tg];
                uint32_t bh1 = *(const uint32_t*)&Bh[n][kb + 2 * tg + 8];
                uint32_t bl0 = *(const uint32_t*)&Bl[n][kb + 2 * tg];
                uint32_t bl1 = *(const uint32_t*)&Bl[n][kb + 2 * tg + 8];
                mma_bf16(acc[t], ah0, ah1, ah2, ah3, bh0, bh1);
                mma_bf16(acc[t], ah0, ah1, ah2, ah3, bl0, bl1);
                mma_bf16(acc[t], al0, al1, al2, al3, bh0, bh1);
            }
        }
        __syncthreads();
    }

    // ---- epilogue: D fragment (g row / g+8 row, cols 2tg..+1 per n-tile)
    {
        int r0 = m0 + w * 16 + g;
        int r1 = r0 + 8;
#pragma unroll
        for (int t = 0; t < 8; t++) {
            int n = t * 8 + 2 * tg;
            if (r0 < M) {
                float2 v = make_float2(acc[t][0], acc[t][1]);
                *(float2*)&g_z[(size_t)(zoff + r0) * F + n] = v;
            }
            if (r1 < M) {
                float2 v = make_float2(acc[t][2], acc[t][3]);
                *(float2*)&g_z[(size_t)(zoff + r1) * F + n] = v;
            }
        }
    }
}

// ---------------- CSR build -------------------------------------------------
__global__ void zero_counts(int n) {
    int i = blockIdx.x * blockDim.x + threadIdx.x;
    if (i < n) { g_cnt[i] = 0; g_cnt2[i] = 0; }
}

__global__ void count_kernel(const int* __restrict__ dst, int E) {
    int i = blockIdx.x * blockDim.x + threadIdx.x;
    if (i < E) atomicAdd(&g_cnt[dst[i]], 1);
}

__global__ void scan1(int n) {
    __shared__ int sh[1024];
    int i = blockIdx.x * 1024 + threadIdx.x;
    int v = (i < n) ? g_cnt[i] : 0;
    sh[threadIdx.x] = v;
    __syncthreads();
    for (int off = 1; off < 1024; off <<= 1) {
        int t = (threadIdx.x >= off) ? sh[threadIdx.x - off] : 0;
        __syncthreads();
        sh[threadIdx.x] += t;
        __syncthreads();
    }
    if (i < n) g_tmp[i] = sh[threadIdx.x];
    if (threadIdx.x == 1023) g_blocksum[blockIdx.x] = sh[1023];
}

__global__ void scan2(int nb) {
    if (threadIdx.x == 0) {
        int run = 0;
        for (int b = 0; b < nb; b++) {
            g_blockoff[b] = run;
            run += g_blocksum[b];
        }
    }
}

__global__ void scan3(int n, int E) {
    int i = blockIdx.x * blockDim.x + threadIdx.x;
    if (i < n) g_rowptr[i] = g_tmp[i] - g_cnt[i] + g_blockoff[i >> 10];
    if (i == 0) g_rowptr[n] = E;
}

__global__ void fill_kernel(const int* __restrict__ src, const int* __restrict__ dst, int E) {
    int i = blockIdx.x * blockDim.x + threadIdx.x;
    if (i < E) {
        int d = dst[i];
        int pos = g_rowptr[d] + atomicAdd(&g_cnt2[d], 1);
        g_src_sorted[pos] = src[i];
    }
}

// ---------------- per-dst-node ONLINE softmax + aggregate (warp per node) ---
__global__ void __launch_bounds__(256) node_kernel(float* __restrict__ out, int NN) {
    int gwid = (blockIdx.x * blockDim.x + threadIdx.x) >> 5;
    int lane = threadIdx.x & 31;
    if (gwid >= NN) return;
    const int node = gwid;
    const int beg = g_rowptr[node];
    const int end = g_rowptr[node + 1];

    const float2* z2 = (const float2*)g_z;
    float2 zd = z2[(size_t)node * 32 + lane];

    float m = -INFINITY;
    float denom = 0.f;
    float2 acc = make_float2(0.f, 0.f);

    int p = beg;
    for (; p + 3 < end; p += 4) {
        int s0 = g_src_sorted[p];
        int s1 = g_src_sorted[p + 1];
        int s2 = g_src_sorted[p + 2];
        int s3 = g_src_sorted[p + 3];
        float2 a0 = z2[(size_t)s0 * 32 + lane];
        float2 a1 = z2[(size_t)s1 * 32 + lane];
        float2 a2 = z2[(size_t)s2 * 32 + lane];
        float2 a3 = z2[(size_t)s3 * 32 + lane];
        float d0 = a0.x * zd.x + a0.y * zd.y;
        float d1 = a1.x * zd.x + a1.y * zd.y;
        float d2 = a2.x * zd.x + a2.y * zd.y;
        float d3 = a3.x * zd.x + a3.y * zd.y;
#pragma unroll
        for (int off = 16; off; off >>= 1) {
            d0 += __shfl_xor_sync(0xffffffffu, d0, off);
            d1 += __shfl_xor_sync(0xffffffffu, d1, off);
            d2 += __shfl_xor_sync(0xffffffffu, d2, off);
            d3 += __shfl_xor_sync(0xffffffffu, d3, off);
        }
        float e0 = d0 > 0.f ? d0 : SLOPE * d0;
        float e1 = d1 > 0.f ? d1 : SLOPE * d1;
        float e2 = d2 > 0.f ? d2 : SLOPE * d2;
        float e3 = d3 > 0.f ? d3 : SLOPE * d3;
        float mn = fmaxf(fmaxf(m, fmaxf(e0, e1)), fmaxf(e2, e3));
        float corr = __expf(m - mn);        // exp(-inf)=0 on first group
        float w0 = __expf(e0 - mn);
        float w1 = __expf(e1 - mn);
        float w2 = __expf(e2 - mn);
        float w3 = __expf(e3 - mn);
        m = mn;
        denom = fmaf(denom, corr, (w0 + w1) + (w2 + w3));
        float sx = fmaf(w0, a0.x, w1 * a1.x) + fmaf(w2, a2.x, w3 * a3.x);
        float sy = fmaf(w0, a0.y, w1 * a1.y) + fmaf(w2, a2.y, w3 * a3.y);
        acc.x = fmaf(acc.x, corr, sx);
        acc.y = fmaf(acc.y, corr, sy);
    }
    for (; p < end; p++) {
        int s = g_src_sorted[p];
        float2 a = z2[(size_t)s * 32 + lane];
        float d0 = a.x * zd.x + a.y * zd.y;
#pragma unroll
        for (int off = 16; off; off >>= 1)
            d0 += __shfl_xor_sync(0xffffffffu, d0, off);
        float e = d0 > 0.f ? d0 : SLOPE * d0;
        float mn = fmaxf(m, e);
        float corr = __expf(m - mn);
        float w = __expf(e - mn);
        m = mn;
        denom = fmaf(denom, corr, w);
        acc.x = fmaf(acc.x, corr, w * a.x);
        acc.y = fmaf(acc.y, corr, w * a.y);
    }

    float2 h = make_float2(0.f, 0.f);
    if (end > beg) {
        float inv = 1.f / denom;
        h.x = acc.x * inv;
        h.y = acc.y * inv;
    }
    // ELU
    h.x = h.x > 0.f ? h.x : expm1f(h.x);
    h.y = h.y > 0.f ? h.y : expm1f(h.y);
    ((float2*)out)[(size_t)node * 32 + lane] = h;
}

// ---------------- launch ----------------------------------------------------
extern "C" void kernel_launch(void* const* d_in, const int* in_sizes, int n_in,
                              void* d_out, int out_size) {
    const float* d_sim  = (const float*)d_in[0];
    const float* mi_sim = (const float*)d_in[1];
    const float* W_d    = (const float*)d_in[2];
    const float* W_mi   = (const float*)d_in[3];
    const int*   src    = (const int*)d_in[4];
    const int*   dst    = (const int*)d_in[5];
    float* out = (float*)d_out;

    const int KD = 383, KM = 495;
    const int ND = in_sizes[0] / KD;
    const int NM = in_sizes[1] / KM;
    const int NN = ND + NM;
    const int E  = in_sizes[4];

    const int nbd = (ND + 127) / 128;
    const int nbm = (NM + 127) / 128;
    gemm_mma<<<nbd + nbm, 256>>>(d_sim, W_d, mi_sim, W_mi, ND, NM, KD, KM);

    zero_counts<<<(NN + 255) / 256, 256>>>(NN);
    count_kernel<<<(E + 255) / 256, 256>>>(dst, E);

    int nb = (NN + 1023) / 1024;
    scan1<<<nb, 1024>>>(NN);
    scan2<<<1, 32>>>(nb);
    scan3<<<(NN + 255) / 256, 256>>>(NN, E);

    fill_kernel<<<(E + 255) / 256, 256>>>(src, dst, E);

    node_kernel<<<(NN * 32 + 255) / 256, 256>>>(out, NN);
}